// round 17
// baseline (speedup 1.0000x reference)
#include <cuda_runtime.h>
#include <cuda_fp16.h>
#include <mma.h>
#include <cstdint>

using namespace nvcuda;

#define CC 2048
#define HWN 4096
#define NCONVB 512
#define NSAMPB 64    // 16 img x 4 K-splits (512 ch each) -> grid 576 = 1.95 waves

// ---------------- device scratch ----------------
__device__ __half g_W1h[128*2048];
__device__ float g_W2t[128*128];
__device__ float g_p1[128*512];
__device__ float g_p2[128*512];
__device__ float g_mean[128];
__device__ float g_istd[128];
__device__ float g_hs4[4][1024*192];   // 4 K-split partials, plain stores
__device__ float g_tf[1024*128];
__device__ float g_tw[1024];
__device__ int   g_cnt;

// ---------------- helpers ----------------
__device__ __forceinline__ void cpasync16(void* s, const void* g) {
    unsigned sa = (unsigned)__cvta_generic_to_shared(s);
    asm volatile("cp.async.cg.shared.global [%0], [%1], 16;\n" :: "r"(sa), "l"(g));
}
__device__ __forceinline__ void cpcommit() { asm volatile("cp.async.commit_group;\n"); }
template<int N> __device__ __forceinline__ void cpwait() {
    asm volatile("cp.async.wait_group %0;\n" :: "n"(N));
}
__device__ __forceinline__ uint32_t h2u(float x, float y) {
    __half2 h = __floats2half2_rn(x, y);
    return *reinterpret_cast<uint32_t*>(&h);
}

// ---------------- prep: W1 -> half, W2 -> transposed, reset out + counter ------------
__global__ void k_prep(const float* __restrict__ W1, const float* __restrict__ W2,
                       float* out) {
    const int bx = blockIdx.x;
    if (bx < 256) {
        int idx = bx*256 + threadIdx.x;
        float4 v = reinterpret_cast<const float4*>(W1)[idx];
        uint2 u; u.x = h2u(v.x, v.y); u.y = h2u(v.z, v.w);
        *reinterpret_cast<uint2*>(g_W1h + idx*4) = u;
    } else if (bx < 320) {
        int idx = (bx - 256)*256 + threadIdx.x;
        int o = idx >> 7, k = idx & 127;
        g_W2t[k*128 + o] = W2[idx];
    } else if (threadIdx.x == 0) {
        out[0] = 0.f;
        g_cnt = 0;
    }
}

// smem: A f16 2 x [64k][136] (17408 B) | W f16 3 x [128ch][72] (18432 B) = 90112 B
#define A_STG 17408
#define W_OFF 34816
#define W_STG 18432
#define DYNB  90112

__global__ __launch_bounds__(256, 2)
void k_fused(const float* __restrict__ feats, const float* __restrict__ W1,
             const float* __restrict__ Wa1,  const int* __restrict__ labels) {
    extern __shared__ char dynC[];
    float* dyn = (float*)dynC;
    __shared__ float r1[256], r2[256];
    __shared__ int s_last;
    const int tid = threadIdx.x;

    if (blockIdx.x < NSAMPB) {
        // ============ sampled path FIRST: exact fp32 conv at 64 label==1 pixels ======
        const int sb = blockIdx.x;
        const int z = sb & 3;            // 4 K-splits of 512 channels
        const int b = sb >> 2;
        float* Fs  = dyn;                    // [64][33]
        float* Ws2 = dyn + 64*33;            // [192][33]
        int*   pix = (int*)(dyn + 64*33 + 192*33);

        if (tid < 64) pix[tid] = 0;
        __syncthreads();
        if (tid < 32) {
            const int lane = tid;
            int probe = 0;
            #pragma unroll
            for (int i = lane; i < 64; i += 32) probe |= labels[2*(i*512)+1];
            unsigned any = __ballot_sync(0xffffffffu, probe != 0);
            const bool is64 = (any == 0u);
            const long long* L64 = (const long long*)labels;
            int base = 0;
            for (int c = 0; c < 128; c++) {
                if (base >= 64) break;
                int p = (c << 5) + lane;
                long long v = is64 ? L64[(size_t)b*HWN + p]
                                   : (long long)labels[(size_t)b*HWN + p];
                bool valid = (v == 1);
                unsigned m = __ballot_sync(0xffffffffu, valid);
                int pre = __popc(m & ((1u << lane) - 1u));
                if (valid && base + pre < 64) pix[base + pre] = p;
                base += __popc(m);
            }
        }
        __syncthreads();

        float acc[4][12];
        #pragma unroll
        for (int i = 0; i < 4; i++)
            #pragma unroll
            for (int j = 0; j < 12; j++) acc[i][j] = 0.f;

        const int pg = tid & 15;
        const int cg = tid >> 4;
        const size_t fb = (size_t)b*CC*HWN;
        const int kbase = z * 512;

        for (int chn = 0; chn < 16; chn++) {
            int k0 = kbase + chn*32;
            __syncthreads();
            #pragma unroll
            for (int i = 0; i < 8; i++) {
                int idx = tid + i*256;
                int px = idx >> 5, kk = idx & 31;
                Fs[px*33 + kk] = feats[fb + (size_t)(k0+kk)*HWN + pix[px]];
            }
            #pragma unroll
            for (int i = 0; i < 24; i++) {
                int idx = tid + i*256;
                int r = idx >> 5, kk = idx & 31;
                Ws2[r*33 + kk] = (r < 128) ? W1[r*CC + k0 + kk]
                                           : Wa1[(r-128)*CC + k0 + kk];
            }
            __syncthreads();
            #pragma unroll 4
            for (int kk = 0; kk < 32; kk++) {
                float fv[4];
                #pragma unroll
                for (int i = 0; i < 4; i++) fv[i] = Fs[(pg*4 + i)*33 + kk];
                #pragma unroll
                for (int j = 0; j < 12; j++) {
                    float w = Ws2[(cg*12 + j)*33 + kk];
                    #pragma unroll
                    for (int i = 0; i < 4; i++) acc[i][j] += fv[i]*w;
                }
            }
        }
        #pragma unroll
        for (int i = 0; i < 4; i++)
            #pragma unroll
            for (int j = 0; j < 12; j++)
                g_hs4[z][(b*64 + pg*4 + i)*192 + cg*12 + j] = acc[i][j];
        return;
    }

    // ===== conv1 stats: f16 wmma, M=128 x N=128, K-chunk 64 (32 chunks) ==============
    const int cb = blockIdx.x - NSAMPB;
    const int b  = cb >> 5;
    const int p0 = (cb & 31) * 128;
    const float* F = feats + (size_t)b*CC*HWN + p0;

    const int wid = tid >> 5;
    const int wr  = wid & 3;    // 32-pixel group
    const int wc  = wid >> 2;   // 64-channel group

    wmma::fragment<wmma::accumulator,16,16,16,half> acc[2][4];
    #pragma unroll
    for (int i = 0; i < 2; i++)
        #pragma unroll
        for (int j = 0; j < 4; j++) wmma::fill_fragment(acc[i][j], __float2half(0.f));

    auto Ah = [&](int s) { return (half*)(dynC + s*A_STG); };            // [64k][136]
    auto Wh = [&](int s) { return (half*)(dynC + W_OFF + (s)*W_STG); };  // [128ch][72]

    float4 ra[8];
    auto ldA = [&](int kc) {
        const float* Fg = F + (size_t)(kc*64)*HWN;
        #pragma unroll
        for (int i = 0; i < 8; i++) {
            int idx = tid + i*256;
            int k = idx >> 5, px4 = (idx & 31) << 2;
            ra[i] = *reinterpret_cast<const float4*>(Fg + (size_t)k*HWN + px4);
        }
    };
    auto stA = [&](int kc) {
        half* Ab = Ah(kc & 1);
        #pragma unroll
        for (int i = 0; i < 8; i++) {
            int idx = tid + i*256;
            int k = idx >> 5, px4 = (idx & 31) << 2;
            uint2 u; u.x = h2u(ra[i].x, ra[i].y); u.y = h2u(ra[i].z, ra[i].w);
            *reinterpret_cast<uint2*>(Ab + k*136 + px4) = u;
        }
    };
    auto issueW = [&](int kc) {
        half* W = Wh(kc % 3);
        const __half* Wg = g_W1h + kc*64;
        #pragma unroll
        for (int i = 0; i < 4; i++) {
            int idx = tid + i*256;
            int ch = idx >> 3, sg = idx & 7;
            cpasync16(W + ch*72 + sg*8, Wg + ch*2048 + sg*8);
        }
        cpcommit();
    };
    auto compute = [&](int kc) {
        const half* Ab = Ah(kc & 1);
        const half* Wb = Wh(kc % 3);
        #pragma unroll
        for (int ks = 0; ks < 64; ks += 16) {
            wmma::fragment<wmma::matrix_a,16,16,16,half,wmma::col_major> af[2];
            #pragma unroll
            for (int i = 0; i < 2; i++)
                wmma::load_matrix_sync(af[i], Ab + ks*136 + wr*32 + i*16, 136);
            wmma::fragment<wmma::matrix_b,16,16,16,half,wmma::col_major> bf[4];
            #pragma unroll
            for (int j = 0; j < 4; j++)
                wmma::load_matrix_sync(bf[j], Wb + (wc*64 + j*16)*72 + ks, 72);
            #pragma unroll
            for (int i = 0; i < 2; i++)
                #pragma unroll
                for (int j = 0; j < 4; j++)
                    wmma::mma_sync(acc[i][j], af[i], bf[j], acc[i][j]);
        }
    };

    issueW(0); issueW(1);
    ldA(0); stA(0);
    ldA(1);
    cpwait<1>();
    __syncthreads();

    for (int kc = 0; kc < 32; kc++) {
        if (kc + 1 < 32) stA(kc + 1);
        if (kc + 2 < 32) ldA(kc + 2);
        compute(kc);
        if (kc + 2 < 32) { issueW(kc + 2); cpwait<1>(); }
        else             { cpwait<0>(); }
        __syncthreads();
    }

    // Epilogue: partials
    half* Cs16 = (half*)dynC;   // [128 px][136]
    #pragma unroll
    for (int i = 0; i < 2; i++)
        #pragma unroll
        for (int j = 0; j < 4; j++)
            wmma::store_matrix_sync(Cs16 + (wr*32 + i*16)*136 + wc*64 + j*16,
                                    acc[i][j], 136, wmma::mem_row_major);
    __syncthreads();
    {
        const int ch = tid & 127;
        const int sg = tid >> 7;
        float s = 0.f, s2 = 0.f;
        #pragma unroll 4
        for (int p = sg*64; p < sg*64 + 64; p++) {
            float v = __half2float(Cs16[p*136 + ch]);
            s += v; s2 += v*v;
        }
        r1[tid] = s; r2[tid] = s2;
        __syncthreads();
        if (tid < 128) {
            g_p1[tid*512 + cb] = r1[tid] + r1[tid+128];
            g_p2[tid*512 + cb] = r2[tid] + r2[tid+128];
        }
    }

    // last conv block computes BN stats (threadfence + ticket)
    __threadfence();
    if (tid == 0) s_last = (atomicAdd(&g_cnt, 1) == NCONVB - 1) ? 1 : 0;
    __syncthreads();
    if (s_last) {
        const int ch = tid & 127;
        const int half_ = tid >> 7;
        float S = 0.f, S2 = 0.f;
        const float4* p1 = reinterpret_cast<const float4*>(g_p1 + ch*512 + half_*256);
        const float4* p2 = reinterpret_cast<const float4*>(g_p2 + ch*512 + half_*256);
        #pragma unroll 4
        for (int i = 0; i < 64; i++) {
            float4 v1 = p1[i], v2 = p2[i];
            S  += v1.x + v1.y + v1.z + v1.w;
            S2 += v2.x + v2.y + v2.z + v2.w;
        }
        r1[tid] = S; r2[tid] = S2;
        __syncthreads();
        if (tid < 128) {
            float Sa  = r1[tid] + r1[tid+128];
            float S2a = r2[tid] + r2[tid+128];
            float m   = Sa  * (1.f/65536.f);
            float var = S2a * (1.f/65536.f) - m*m;
            g_mean[tid] = m;
            g_istd[tid] = rsqrtf(var + 1e-5f);
        }
    }
}

// ---------------- per-8-pixel proj: W2t staged in smem, grid 128 ----------------
#define PJ_XR 16896            // Ws 128*132
#define PJ_AR (PJ_XR + 8*132)  // xr 8*132
#define PJ_SQ (PJ_AR + 8*64)   // ar 8*64
#define PJ_RI (PJ_SQ + 8*128)  // rsq 8*128
#define PJ_TOT (PJ_RI + 8)     // rinv 8
#define PJ_DYNB (PJ_TOT*4)

__global__ __launch_bounds__(256) void k_proj(
        const float* __restrict__ b1, const float* __restrict__ gamma,
        const float* __restrict__ beta, const float* __restrict__ b2,
        const float* __restrict__ ba1, const float* __restrict__ Wa2,
        const float* __restrict__ ba2) {
    extern __shared__ float sm[];
    float* Ws  = sm;
    float* xr  = sm + PJ_XR;
    float* ar  = sm + PJ_AR;
    float* rsq = sm + PJ_SQ;
    float* rinv= sm + PJ_RI;
    const int t = threadIdx.x;
    const int pb = blockIdx.x * 8;

    #pragma unroll
    for (int i = 0; i < 16; i++) {
        int idx = t + i*256;
        int k = idx >> 5, o4 = (idx & 31) << 2;
        float4 v = reinterpret_cast<const float4*>(g_W2t)[idx];
        float* d = Ws + k*132 + o4;
        d[0]=v.x; d[1]=v.y; d[2]=v.z; d[3]=v.w;
    }
    #pragma unroll
    for (int i = 0; i < 4; i++) {
        int idx = t + i*256;
        int px = idx >> 7, ch = idx & 127;
        int o = (pb + px)*192 + ch;
        float h = g_hs4[0][o] + g_hs4[1][o] + g_hs4[2][o] + g_hs4[3][o] + b1[ch];
        float xn = (h - (g_mean[ch] + b1[ch])) * g_istd[ch] * gamma[ch] + beta[ch];
        xr[px*132 + ch] = fmaxf(xn, 0.f);
    }
    #pragma unroll
    for (int i = 0; i < 2; i++) {
        int idx = t + i*256;
        int px = idx >> 6, ch = idx & 63;
        int o = (pb + px)*192 + 128 + ch;
        float ha = g_hs4[0][o] + g_hs4[1][o] + g_hs4[2][o] + g_hs4[3][o];
        ar[px*64 + ch] = fmaxf(ha + ba1[ch], 0.f);
    }
    __syncthreads();

    {
        int px = t >> 5, lane = t & 31;
        float z = Wa2[lane]*ar[px*64 + lane] + Wa2[lane+32]*ar[px*64 + lane+32];
        #pragma unroll
        for (int o = 16; o > 0; o >>= 1) z += __shfl_down_sync(0xffffffffu, z, o);
        if (lane == 0) g_tw[pb + px] = 1.f / (1.f + expf(-(z + ba2[0])));
    }

    const int ch  = t & 127;
    const int grp = t >> 7;
    float acc[4];
    #pragma unroll
    for (int j = 0; j < 4; j++) acc[j] = b2[ch];
    #pragma unroll 4
    for (int k = 0; k < 128; k++) {
        float w = Ws[k*132 + ch];
        #pragma unroll
        for (int j = 0; j < 4; j++) acc[j] += w * xr[(grp*4 + j)*132 + k];
    }
    #pragma unroll
    for (int j = 0; j < 4; j++) rsq[(grp*4 + j)*128 + ch] = acc[j]*acc[j];
    __syncthreads();
    {
        int px = t >> 5, lane = t & 31;
        float s = rsq[px*128 + lane] + rsq[px*128 + lane+32]
                + rsq[px*128 + lane+64] + rsq[px*128 + lane+96];
        #pragma unroll
        for (int o = 16; o > 0; o >>= 1) s += __shfl_down_sync(0xffffffffu, s, o);
        if (lane == 0) rinv[px] = 1.f / fmaxf(sqrtf(s), 1e-12f);
    }
    __syncthreads();
    #pragma unroll
    for (int j = 0; j < 4; j++)
        g_tf[(pb + grp*4 + j)*128 + ch] = acc[j] * rinv[grp*4 + j];
}

// ---------------- contrastive loss + final (grid 128, atomic into out) ---------------
__global__ __launch_bounds__(256) void k_loss(float* out) {
    __shared__ float tf[64*132];
    __shared__ float tw[64];
    __shared__ float red[8];
    const int t = threadIdx.x;
    const int b  = blockIdx.x >> 3;
    const int rg = blockIdx.x & 7;
    const int wid = t >> 5;
    const int lane = t & 31;

    #pragma unroll
    for (int i = 0; i < 8; i++) {
        int idx = t + i*256;
        int row = idx >> 5, c4 = (idx & 31) << 2;
        float4 v = reinterpret_cast<const float4*>(g_tf + b*8192)[idx];
        *reinterpret_cast<float4*>(tf + row*132 + c4) = v;
    }
    if (t < 64) tw[t] = g_tw[b*64 + t];
    __syncthreads();

    const int i = rg*8 + wid;
    const int j0 = lane, j1 = lane + 32;

    float a0 = 0.f, a1 = 0.f;
    const float4* fi = reinterpret_cast<const float4*>(tf + i*132);
    const float4* c0 = reinterpret_cast<const float4*>(tf + j0*132);
    const float4* c1 = reinterpret_cast<const float4*>(tf + j1*132);
    #pragma unroll 8
    for (int k4 = 0; k4 < 32; k4++) {
        float4 a = fi[k4];
        float4 v0 = c0[k4], v1 = c1[k4];
        a0 += a.x*v0.x + a.y*v0.y + a.z*v0.z + a.w*v0.w;
        a1 += a.x*v1.x + a.y*v1.y + a.z*v1.z + a.w*v1.w;
    }
    float s0 = a0*10.f, s1 = a1*10.f;
    float e0 = expf(s0), e1 = expf(s1);
    float d = e0 + e1;
    #pragma unroll
    for (int o = 16; o > 0; o >>= 1) d += __shfl_xor_sync(0xffffffffu, d, o);

    float twi = tw[i];
    float lacc = 0.f;
    if (s0 > 0.7f && j0 != i) lacc += twi * tw[j0] * logf(e0/d + 1e-10f);
    if (s1 > 0.7f && j1 != i) lacc += twi * tw[j1] * logf(e1/d + 1e-10f);
    #pragma unroll
    for (int o = 16; o > 0; o >>= 1) lacc += __shfl_xor_sync(0xffffffffu, lacc, o);
    if (lane == 0) red[wid] = lacc;
    __syncthreads();

    if (t == 0) {
        float blk = red[0]+red[1]+red[2]+red[3]+red[4]+red[5]+red[6]+red[7];
        float tsum = 0.f;
        #pragma unroll 8
        for (int j = 0; j < 64; j++) tsum += tw[j];
        atomicAdd(out, (-(0.1f/0.07f) * blk / tsum) * (0.1f / 16.0f));
    }
}

// ---------------- launch ----------------
extern "C" void kernel_launch(void* const* d_in, const int* in_sizes, int n_in,
                              void* d_out, int out_size) {
    const float* feats = (const float*)d_in[0];
    const int*   labels= (const int*)d_in[1];
    const float* W1   = (const float*)d_in[2];
    const float* b1   = (const float*)d_in[3];
    const float* gamma= (const float*)d_in[4];
    const float* beta = (const float*)d_in[5];
    const float* W2   = (const float*)d_in[6];
    const float* b2   = (const float*)d_in[7];
    const float* Wa1  = (const float*)d_in[8];
    const float* ba1  = (const float*)d_in[9];
    const float* Wa2  = (const float*)d_in[10];
    const float* ba2  = (const float*)d_in[11];

    cudaFuncSetAttribute(k_fused, cudaFuncAttributeMaxDynamicSharedMemorySize, DYNB);
    cudaFuncSetAttribute(k_proj,  cudaFuncAttributeMaxDynamicSharedMemorySize, PJ_DYNB);

    k_prep<<<321, 256>>>(W1, W2, (float*)d_out);
    k_fused<<<NSAMPB + NCONVB, 256, DYNB>>>(feats, W1, Wa1, labels);
    k_proj<<<128, 256, PJ_DYNB>>>(b1, gamma, beta, b2, ba1, Wa2, ba2);
    k_loss<<<128, 256>>>((float*)d_out);
}